// round 11
// baseline (speedup 1.0000x reference)
#include <cuda_runtime.h>

#define IN_SIZE 448
#define OUT_SIZE 224
#define BATCH 64
#define NTHREADS 224
#define RPB 8
#define MAXROWS 17          // max input rows a block needs (stride<=2.005: 7*2.005->15, +1 end, +1 incl)
#define SMW 452             // staged row width in floats (= 113 float4), 16B-aligned row stride

// fast sigmoid(10z): MUFU-based; saturates exactly to 0/1 for large |10z|.
__device__ __forceinline__ float sig10f(float z) {
    return 1.0f / (1.0f + __expf(-10.0f * z));
}

// ---------------------------------------------------------------------------
// Staged kernel. grid=(28 rowgroups, 64 batch, 3 ch), block=224.
// Stage the block's exact input-row window (dense float4 loads), then take all
// bilinear taps from shared memory.
// ---------------------------------------------------------------------------
__global__ void __launch_bounds__(NTHREADS, 6) racnn_stage(
    const float* __restrict__ images,
    const float* __restrict__ locs,
    float* __restrict__ out)
{
    __shared__ float  sm[MAXROWS * SMW];
    __shared__ float4 s_rowe[RPB];   // {lr0*SMW (int bits), lr1*SMW (int bits), a0, a1}

    const int rg  = blockIdx.x;      // 0..27
    const int b   = blockIdx.y;
    const int ch  = blockIdx.z;
    const int tid = threadIdx.x;
    const int jr0 = rg * RPB;

    // ---- per-batch crop params (broadcast; exact reference fp32 ordering) ----
    float tx = locs[b * 3 + 0];
    float ty = locs[b * 3 + 1];
    float tl = locs[b * 3 + 2];

    tl = fmaxf(tl, 448.0f / 3.0f);
    tx = fminf(fmaxf(tx, tl), (float)IN_SIZE - tl);
    ty = fminf(fmaxf(ty, tl), (float)IN_SIZE - tl);

    const float w_off = fmaxf(floorf(tx - tl), 0.0f);
    const float h_off = fmaxf(floorf(ty - tl), 0.0f);
    const float w_end = fminf(floorf(tx + tl), (float)IN_SIZE);
    const float h_end = fminf(floorf(ty + tl), (float)IN_SIZE);

    const float dr = w_end - w_off - 1.0f;
    const float dc = h_end - h_off - 1.0f;

    // ---- block input-row window (uniform across threads) ----
    const int rbeg = (int)fminf(fmaxf(floorf(w_off + ((float)jr0 * dr) / 223.0f), 0.0f), 447.0f);
    const int r7   = (int)fminf(fmaxf(floorf(w_off + ((float)(jr0 + 7) * dr) / 223.0f), 0.0f), 447.0f);
    const int rend = min(r7 + 1, IN_SIZE - 1);
    const int nrows = rend - rbeg + 1;           // <= MAXROWS

    // ---- column window (batch-uniform) ----
    const int cw0  = ((int)h_off) & ~3;          // 16B-aligned start
    const int cend = min((int)h_end, IN_SIZE - 1);  // last column any tap reads

    // ---- row entries: threads 0..7 ----
    if (tid < RPB) {
        const float src_r = w_off + ((float)(jr0 + tid) * dr) / 223.0f;
        float r0 = fminf(fmaxf(floorf(src_r), 0.0f), (float)(IN_SIZE - 1));
        const float wr = src_r - r0;
        const int r0i = (int)r0;
        const int r1i = min(r0i + 1, IN_SIZE - 1);
        const float mrow0 = sig10f((float)r0i - w_off) - sig10f((float)r0i - w_end);
        const float mrow1 = sig10f((float)r1i - w_off) - sig10f((float)r1i - w_end);
        float4 e;
        e.x = __int_as_float((r0i - rbeg) * SMW);
        e.y = __int_as_float((r1i - rbeg) * SMW);
        e.z = (1.0f - wr) * mrow0;
        e.w = wr * mrow1;
        s_rowe[tid] = e;
    }

    // ---- col entry: per thread ----
    const float src_c = h_off + ((float)tid * dc) / 223.0f;
    float c0 = fminf(fmaxf(floorf(src_c), 0.0f), (float)(IN_SIZE - 1));
    const float wc = src_c - c0;
    const int c0i = (int)c0;
    const int c1i = min(c0i + 1, IN_SIZE - 1);
    const float mcol0 = sig10f((float)c0i - h_off) - sig10f((float)c0i - h_end);
    const float mcol1 = sig10f((float)c1i - h_off) - sig10f((float)c1i - h_end);
    const float b0 = (1.0f - wc) * mcol0;
    const float b1 = wc * mcol1;
    const int sc0 = c0i - cw0;     // in [0, SMW)
    const int sc1 = c1i - cw0;

    // ---- stage: dense float4 loads of the row x col window ----
    const int img_base = (b * 3 + ch) * (IN_SIZE * IN_SIZE);
    const int total4 = nrows * 113;
    for (int i = tid; i < total4; i += NTHREADS) {
        const int r  = i / 113;                  // constant divisor -> mul+shift
        const int c4 = i - r * 113;
        const int gc = cw0 + c4 * 4;
        if (gc <= cend && gc <= IN_SIZE - 4) {   // need-window & in-row bounds
            const float4 v = __ldg((const float4*)(images + img_base + (rbeg + r) * IN_SIZE + gc));
            *(float4*)&sm[r * SMW + (gc - cw0)] = v;
        }
    }
    __syncthreads();

    // ---- compute: all taps from shared memory ----
    const int out_base = (b * 3 + ch) * (OUT_SIZE * OUT_SIZE) + jr0 * OUT_SIZE + tid;

#pragma unroll
    for (int r = 0; r < RPB; r++) {
        const float4 re = s_rowe[r];
        const int   o0 = __float_as_int(re.x);
        const int   o1 = __float_as_int(re.y);
        const float a0 = re.z;
        const float a1 = re.w;

        const float x00 = sm[o0 + sc0];
        const float x01 = sm[o0 + sc1];
        const float x10 = sm[o1 + sc0];
        const float x11 = sm[o1 + sc1];

        const float top = fmaf(b1, x01, b0 * x00);
        const float bot = fmaf(b1, x11, b0 * x10);
        out[out_base + r * OUT_SIZE] = fmaf(a1, bot, a0 * top);
    }
}

extern "C" void kernel_launch(void* const* d_in, const int* in_sizes, int n_in,
                              void* d_out, int out_size) {
    const float* images = (const float*)d_in[0];
    const float* locs   = (const float*)d_in[1];
    float* out = (float*)d_out;

    dim3 grid(OUT_SIZE / RPB, BATCH, 3);
    racnn_stage<<<grid, NTHREADS>>>(images, locs, out);
}

// round 12
// speedup vs baseline: 1.3586x; 1.3586x over previous
#include <cuda_runtime.h>

#define IN_SIZE 448
#define OUT_SIZE 224
#define BATCH 64
#define NTHREADS 224
#define ROWS_PER_BLK 8

// fast sigmoid(10z): MUFU-based; saturates exactly to 0/1 for large |10z|.
__device__ __forceinline__ float sig10f(float z) {
    return 1.0f / (1.0f + __expf(-10.0f * z));
}

// ---------------------------------------------------------------------------
// Fused gather kernel (R7 champion shape) + vertical tap reuse:
// row r's bottom input row == row r+1's top input row for ~2/3 of rows, and
// the test is block-uniform -> skip 6 of 12 loads on those rows.
// grid=(28, 64), block=224.
// ---------------------------------------------------------------------------
__global__ void __launch_bounds__(NTHREADS) racnn_fused(
    const float* __restrict__ images,
    const float* __restrict__ locs,
    float* __restrict__ out)
{
    __shared__ float4 s_rowe[ROWS_PER_BLK];  // {r0off(int bits), r1off(int bits), a0, a1}

    const int jr0 = blockIdx.x * ROWS_PER_BLK;
    const int b   = blockIdx.y;
    const int jc  = threadIdx.x;

    // ---- per-batch crop params (broadcast) ----
    float tx = locs[b * 3 + 0];
    float ty = locs[b * 3 + 1];
    float tl = locs[b * 3 + 2];

    tl = fmaxf(tl, 448.0f / 3.0f);
    tx = fminf(fmaxf(tx, tl), (float)IN_SIZE - tl);
    ty = fminf(fmaxf(ty, tl), (float)IN_SIZE - tl);

    const float w_off = fmaxf(floorf(tx - tl), 0.0f);
    const float h_off = fmaxf(floorf(ty - tl), 0.0f);
    const float w_end = fminf(floorf(tx + tl), (float)IN_SIZE);
    const float h_end = fminf(floorf(ty + tl), (float)IN_SIZE);

    // ---- row entries: threads 0..7 ----
    if (jc < ROWS_PER_BLK) {
        const float jf = (float)(jr0 + jc);
        const float src_r = w_off + (jf * (w_end - w_off - 1.0f)) / (float)(OUT_SIZE - 1);
        float r0 = fminf(fmaxf(floorf(src_r), 0.0f), (float)(IN_SIZE - 1));
        const float wr = src_r - r0;
        const int r0i = (int)r0;
        const int r1i = min(r0i + 1, IN_SIZE - 1);
        const float mrow0 = sig10f((float)r0i - w_off) - sig10f((float)r0i - w_end);
        const float mrow1 = sig10f((float)r1i - w_off) - sig10f((float)r1i - w_end);
        float4 e;
        e.x = __int_as_float(r0i * IN_SIZE);
        e.y = __int_as_float(r1i * IN_SIZE);
        e.z = (1.0f - wr) * mrow0;
        e.w = wr * mrow1;
        s_rowe[jc] = e;
    }

    // ---- col entry: per thread ----
    const float jf = (float)jc;
    const float src_c = h_off + (jf * (h_end - h_off - 1.0f)) / (float)(OUT_SIZE - 1);
    float c0 = fminf(fmaxf(floorf(src_c), 0.0f), (float)(IN_SIZE - 1));
    const float wc = src_c - c0;
    const int c0i = (int)c0;
    const int c1i = min(c0i + 1, IN_SIZE - 1);
    const float mcol0 = sig10f((float)c0i - h_off) - sig10f((float)c0i - h_end);
    const float mcol1 = sig10f((float)c1i - h_off) - sig10f((float)c1i - h_end);
    const float b0 = (1.0f - wc) * mcol0;
    const float b1 = wc * mcol1;

    __syncthreads();

    const int img_base = b * 3 * IN_SIZE * IN_SIZE;
    const int out_base = b * 3 * OUT_SIZE * OUT_SIZE + jr0 * OUT_SIZE + jc;

    // ---- gather with vertical reuse ----
    int prev_p1 = -1;                    // previous row's bottom input-row base
    float y0[3], y1[3];                  // taps of prev bottom row (c0, c1) x ch

#pragma unroll
    for (int r = 0; r < ROWS_PER_BLK; r++) {
        const float4 re = s_rowe[r];
        const int   p0 = img_base + __float_as_int(re.x);
        const int   p1 = img_base + __float_as_int(re.y);
        const float a0 = re.z;
        const float a1 = re.w;

        float x00[3], x01[3];
        if (p0 == prev_p1) {             // block-uniform branch: reuse prev bottom taps
#pragma unroll
            for (int ch = 0; ch < 3; ch++) { x00[ch] = y0[ch]; x01[ch] = y1[ch]; }
        } else {
#pragma unroll
            for (int ch = 0; ch < 3; ch++) {
                const int cofs = ch * (IN_SIZE * IN_SIZE);
                x00[ch] = __ldg(images + p0 + cofs + c0i);
                x01[ch] = __ldg(images + p0 + cofs + c1i);
            }
        }

        // bottom row: always load, becomes next row's candidate top
#pragma unroll
        for (int ch = 0; ch < 3; ch++) {
            const int cofs = ch * (IN_SIZE * IN_SIZE);
            y0[ch] = __ldg(images + p1 + cofs + c0i);
            y1[ch] = __ldg(images + p1 + cofs + c1i);
        }
        prev_p1 = p1;

#pragma unroll
        for (int ch = 0; ch < 3; ch++) {
            const float top = fmaf(b1, x01[ch], b0 * x00[ch]);
            const float bot = fmaf(b1, y1[ch], b0 * y0[ch]);
            const float v = fmaf(a1, bot, a0 * top);
            __stcs(out + out_base + ch * (OUT_SIZE * OUT_SIZE) + r * OUT_SIZE, v);
        }
    }
}

extern "C" void kernel_launch(void* const* d_in, const int* in_sizes, int n_in,
                              void* d_out, int out_size) {
    const float* images = (const float*)d_in[0];
    const float* locs   = (const float*)d_in[1];
    float* out = (float*)d_out;

    dim3 grid(OUT_SIZE / ROWS_PER_BLK, BATCH);
    racnn_fused<<<grid, NTHREADS>>>(images, locs, out);
}

// round 13
// speedup vs baseline: 1.3706x; 1.0088x over previous
#include <cuda_runtime.h>

#define IN_SIZE 448
#define OUT_SIZE 224
#define BATCH 64
#define NTHREADS 224
#define ROWS_PER_BLK 8

// fast sigmoid(10z): MUFU-based; saturates exactly to 0/1 for large |10z|.
__device__ __forceinline__ float sig10f(float z) {
    return 1.0f / (1.0f + __expf(-10.0f * z));
}

// ---------------------------------------------------------------------------
// Champion shape (grid 28x64, block 224, RPB 8) + vertical tap reuse (R12)
// + launch_bounds(224,6)/plain stores (R10's best-core traits).
// ---------------------------------------------------------------------------
__global__ void __launch_bounds__(NTHREADS, 6) racnn_fused(
    const float* __restrict__ images,
    const float* __restrict__ locs,
    float* __restrict__ out)
{
    __shared__ float4 s_rowe[ROWS_PER_BLK];  // {r0off(int bits), r1off(int bits), a0, a1}

    const int jr0 = blockIdx.x * ROWS_PER_BLK;
    const int b   = blockIdx.y;
    const int jc  = threadIdx.x;

    // ---- per-batch crop params (broadcast) ----
    float tx = locs[b * 3 + 0];
    float ty = locs[b * 3 + 1];
    float tl = locs[b * 3 + 2];

    tl = fmaxf(tl, 448.0f / 3.0f);
    tx = fminf(fmaxf(tx, tl), (float)IN_SIZE - tl);
    ty = fminf(fmaxf(ty, tl), (float)IN_SIZE - tl);

    const float w_off = fmaxf(floorf(tx - tl), 0.0f);
    const float h_off = fmaxf(floorf(ty - tl), 0.0f);
    const float w_end = fminf(floorf(tx + tl), (float)IN_SIZE);
    const float h_end = fminf(floorf(ty + tl), (float)IN_SIZE);

    // ---- row entries: threads 0..7 ----
    if (jc < ROWS_PER_BLK) {
        const float jf = (float)(jr0 + jc);
        const float src_r = w_off + (jf * (w_end - w_off - 1.0f)) / (float)(OUT_SIZE - 1);
        float r0 = fminf(fmaxf(floorf(src_r), 0.0f), (float)(IN_SIZE - 1));
        const float wr = src_r - r0;
        const int r0i = (int)r0;
        const int r1i = min(r0i + 1, IN_SIZE - 1);
        const float mrow0 = sig10f((float)r0i - w_off) - sig10f((float)r0i - w_end);
        const float mrow1 = sig10f((float)r1i - w_off) - sig10f((float)r1i - w_end);
        float4 e;
        e.x = __int_as_float(r0i * IN_SIZE);
        e.y = __int_as_float(r1i * IN_SIZE);
        e.z = (1.0f - wr) * mrow0;
        e.w = wr * mrow1;
        s_rowe[jc] = e;
    }

    // ---- col entry: per thread ----
    const float jf = (float)jc;
    const float src_c = h_off + (jf * (h_end - h_off - 1.0f)) / (float)(OUT_SIZE - 1);
    float c0 = fminf(fmaxf(floorf(src_c), 0.0f), (float)(IN_SIZE - 1));
    const float wc = src_c - c0;
    const int c0i = (int)c0;
    const int c1i = min(c0i + 1, IN_SIZE - 1);
    const float mcol0 = sig10f((float)c0i - h_off) - sig10f((float)c0i - h_end);
    const float mcol1 = sig10f((float)c1i - h_off) - sig10f((float)c1i - h_end);
    const float b0 = (1.0f - wc) * mcol0;
    const float b1 = wc * mcol1;

    __syncthreads();

    const int img_base = b * 3 * IN_SIZE * IN_SIZE;
    const int out_base = b * 3 * OUT_SIZE * OUT_SIZE + jr0 * OUT_SIZE + jc;

    // ---- gather with vertical reuse ----
    int prev_p1 = -1;
    float y0[3], y1[3];

#pragma unroll
    for (int r = 0; r < ROWS_PER_BLK; r++) {
        const float4 re = s_rowe[r];
        const int   p0 = img_base + __float_as_int(re.x);
        const int   p1 = img_base + __float_as_int(re.y);
        const float a0 = re.z;
        const float a1 = re.w;

        float x00[3], x01[3];
        if (p0 == prev_p1) {             // block-uniform: reuse prev bottom taps
#pragma unroll
            for (int ch = 0; ch < 3; ch++) { x00[ch] = y0[ch]; x01[ch] = y1[ch]; }
        } else {
#pragma unroll
            for (int ch = 0; ch < 3; ch++) {
                const int cofs = ch * (IN_SIZE * IN_SIZE);
                x00[ch] = __ldg(images + p0 + cofs + c0i);
                x01[ch] = __ldg(images + p0 + cofs + c1i);
            }
        }

#pragma unroll
        for (int ch = 0; ch < 3; ch++) {
            const int cofs = ch * (IN_SIZE * IN_SIZE);
            y0[ch] = __ldg(images + p1 + cofs + c0i);
            y1[ch] = __ldg(images + p1 + cofs + c1i);
        }
        prev_p1 = p1;

#pragma unroll
        for (int ch = 0; ch < 3; ch++) {
            const float top = fmaf(b1, x01[ch], b0 * x00[ch]);
            const float bot = fmaf(b1, y1[ch], b0 * y0[ch]);
            out[out_base + ch * (OUT_SIZE * OUT_SIZE) + r * OUT_SIZE] =
                fmaf(a1, bot, a0 * top);
        }
    }
}

extern "C" void kernel_launch(void* const* d_in, const int* in_sizes, int n_in,
                              void* d_out, int out_size) {
    const float* images = (const float*)d_in[0];
    const float* locs   = (const float*)d_in[1];
    float* out = (float*)d_out;

    dim3 grid(OUT_SIZE / ROWS_PER_BLK, BATCH);
    racnn_fused<<<grid, NTHREADS>>>(images, locs, out);
}

// round 14
// speedup vs baseline: 1.4856x; 1.0839x over previous
#include <cuda_runtime.h>

#define IN_SIZE 448
#define OUT_SIZE 224
#define BATCH 64
#define NTHREADS 224
#define ROWS_PER_BLK 4

// fast sigmoid(10z): MUFU-based; saturates exactly to 0/1 for large |10z|.
__device__ __forceinline__ float sig10f(float z) {
    return 1.0f / (1.0f + __expf(-10.0f * z));
}

// ---------------------------------------------------------------------------
// RPB=4 (fine-grained blocks -> small wave tail), saturation fast path for the
// column masks (cuts the doubled prologue), __stcs streaming stores.
// grid=(56, 64), block=224.
// ---------------------------------------------------------------------------
__global__ void __launch_bounds__(NTHREADS) racnn_fused(
    const float* __restrict__ images,
    const float* __restrict__ locs,
    float* __restrict__ out)
{
    __shared__ float4 s_rowe[ROWS_PER_BLK];  // {r0off(int bits), r1off(int bits), a0, a1}

    const int jr0 = blockIdx.x * ROWS_PER_BLK;
    const int b   = blockIdx.y;
    const int jc  = threadIdx.x;

    // ---- per-batch crop params (broadcast) ----
    float tx = locs[b * 3 + 0];
    float ty = locs[b * 3 + 1];
    float tl = locs[b * 3 + 2];

    tl = fmaxf(tl, 448.0f / 3.0f);
    tx = fminf(fmaxf(tx, tl), (float)IN_SIZE - tl);
    ty = fminf(fmaxf(ty, tl), (float)IN_SIZE - tl);

    const float w_off = fmaxf(floorf(tx - tl), 0.0f);
    const float h_off = fmaxf(floorf(ty - tl), 0.0f);
    const float w_end = fminf(floorf(tx + tl), (float)IN_SIZE);
    const float h_end = fminf(floorf(ty + tl), (float)IN_SIZE);

    // ---- row entries: threads 0..3 ----
    if (jc < ROWS_PER_BLK) {
        const float jf = (float)(jr0 + jc);
        const float src_r = w_off + (jf * (w_end - w_off - 1.0f)) / (float)(OUT_SIZE - 1);
        float r0 = fminf(fmaxf(floorf(src_r), 0.0f), (float)(IN_SIZE - 1));
        const float wr = src_r - r0;
        const int r0i = (int)r0;
        const int r1i = min(r0i + 1, IN_SIZE - 1);
        const float mrow0 = sig10f((float)r0i - w_off) - sig10f((float)r0i - w_end);
        const float mrow1 = sig10f((float)r1i - w_off) - sig10f((float)r1i - w_end);
        float4 e;
        e.x = __int_as_float(r0i * IN_SIZE);
        e.y = __int_as_float(r1i * IN_SIZE);
        e.z = (1.0f - wr) * mrow0;
        e.w = wr * mrow1;
        s_rowe[jc] = e;
    }

    // ---- col entry: per thread; saturation fast path for middle warps ----
    // Col stride >= 297/223 = 1.332 -> for 32<=jc<192 the mask args exceed
    // ~41 in magnitude with the right signs -> mcol == 1 exactly in fp32.
    // Branch is warp-uniform (only warps 0 and 6 evaluate MUFUs).
    const float jf = (float)jc;
    const float src_c = h_off + (jf * (h_end - h_off - 1.0f)) / (float)(OUT_SIZE - 1);
    float c0 = fminf(fmaxf(floorf(src_c), 0.0f), (float)(IN_SIZE - 1));
    const float wc = src_c - c0;
    const int c0i = (int)c0;
    const int c1i = min(c0i + 1, IN_SIZE - 1);

    float mcol0 = 1.0f, mcol1 = 1.0f;
    if (jc < 32 || jc >= 192) {
        mcol0 = sig10f((float)c0i - h_off) - sig10f((float)c0i - h_end);
        mcol1 = sig10f((float)c1i - h_off) - sig10f((float)c1i - h_end);
    }
    const float b0 = (1.0f - wc) * mcol0;
    const float b1 = wc * mcol1;

    __syncthreads();

    const int img_base = b * 3 * IN_SIZE * IN_SIZE;
    const int out_base = b * 3 * OUT_SIZE * OUT_SIZE + jr0 * OUT_SIZE + jc;

    // ---- gather: one row per iteration, 12-load batches ----
#pragma unroll
    for (int r = 0; r < ROWS_PER_BLK; r++) {
        const float4 re = s_rowe[r];
        const int   p0 = img_base + __float_as_int(re.x);
        const int   p1 = img_base + __float_as_int(re.y);
        const float a0 = re.z;
        const float a1 = re.w;

        float x00[3], x01[3], x10[3], x11[3];
#pragma unroll
        for (int ch = 0; ch < 3; ch++) {
            const int cofs = ch * (IN_SIZE * IN_SIZE);
            x00[ch] = __ldg(images + p0 + cofs + c0i);
            x01[ch] = __ldg(images + p0 + cofs + c1i);
            x10[ch] = __ldg(images + p1 + cofs + c0i);
            x11[ch] = __ldg(images + p1 + cofs + c1i);
        }
#pragma unroll
        for (int ch = 0; ch < 3; ch++) {
            const float top = fmaf(b1, x01[ch], b0 * x00[ch]);
            const float bot = fmaf(b1, x11[ch], b0 * x10[ch]);
            const float v = fmaf(a1, bot, a0 * top);
            __stcs(out + out_base + ch * (OUT_SIZE * OUT_SIZE) + r * OUT_SIZE, v);
        }
    }
}

extern "C" void kernel_launch(void* const* d_in, const int* in_sizes, int n_in,
                              void* d_out, int out_size) {
    const float* images = (const float*)d_in[0];
    const float* locs   = (const float*)d_in[1];
    float* out = (float*)d_out;

    dim3 grid(OUT_SIZE / ROWS_PER_BLK, BATCH);
    racnn_fused<<<grid, NTHREADS>>>(images, locs, out);
}